// round 1
// baseline (speedup 1.0000x reference)
#include <cuda_runtime.h>
#include <math.h>

static constexpr int kT = 5, kB = 512, kNA = 16, kS = 64, kA = 16;
static constexpr int kHID = 64, kH = 4, kFD = 256, kLAT = 128;
static constexpr int kN = kB * kNA;        // 8192 nodes
static constexpr int kFIN = 80;
static constexpr int kM = kN * kT;         // 40960 rows

// -------- scratch (static device globals; no runtime allocation) --------
__device__ float g_xl0[(size_t)kM * kFD];
__device__ float g_x1 [(size_t)kM * kFD];
__device__ float g_xl1[(size_t)kM * kFD];
__device__ float g_seq[(size_t)kB * kT * kFD];
__device__ float g_qkv[(size_t)kB * kT * 3 * kFD];
__device__ float g_ctx4[(size_t)kB * kFD];
__device__ float g_feat[(size_t)kB * kFD];
__device__ float g_blog[(size_t)kB * kS];

// ===================================================================
// Kernel A: build node features implicitly and compute xl0 = nodes @ w0^T
// Exploit: belief features are zero except node a==0 (gets signals).
// One block per node n; 256 threads = output columns.
// ===================================================================
__global__ __launch_bounds__(256)
void build_lin0(const float* __restrict__ signals,     // (T,B,S)
                const float* __restrict__ nact,        // (T,B,NA*A)
                const float* __restrict__ w0,          // (FD, FIN)
                float* __restrict__ xl0) {             // (N,T,FD)
    int n = blockIdx.x;
    int b = n >> 4, a = n & 15;
    __shared__ float Wa[16 * 256];      // transposed: Wa[k][o]
    __shared__ float act_s[kT][16];
    __shared__ float sig_s[kT][64];
    int tid = threadIdx.x;
#pragma unroll
    for (int i = 0; i < 16; i++)
        Wa[i * 256 + tid] = w0[tid * kFIN + 64 + i];
    if (tid < kT * 16) {
        int t = tid >> 4, k = tid & 15;
        act_s[t][k] = nact[((size_t)t * kB + b) * (kNA * kA) + a * kA + k];
    }
    if (a == 0) {
        for (int i = tid; i < kT * 64; i += 256) {
            int t = i >> 6, c = i & 63;
            sig_s[t][c] = signals[((size_t)t * kB + b) * kS + c];
        }
    }
    __syncthreads();
    int o = tid;
    float acc[kT] = {0.f, 0.f, 0.f, 0.f, 0.f};
#pragma unroll
    for (int k = 0; k < 16; k++) {
        float w = Wa[k * 256 + o];
#pragma unroll
        for (int t = 0; t < kT; t++) acc[t] += act_s[t][k] * w;
    }
    if (a == 0) {
        for (int c = 0; c < 64; c++) {
            float w = w0[o * kFIN + c];
#pragma unroll
            for (int t = 0; t < kT; t++) acc[t] += sig_s[t][c] * w;
        }
    }
#pragma unroll
    for (int t = 0; t < kT; t++)
        xl0[((size_t)n * kT + t) * kFD + o] = acc[t];
}

// ===================================================================
// Kernel B: GAT aggregation layer 0 (all 16 dst nodes) + bias + relu.
// One block per (group, t). Graph: dense 16x16 incl. self-loop.
// ===================================================================
__global__ __launch_bounds__(256)
void gat_agg0(const float* __restrict__ xl,
              const float* __restrict__ asrc, const float* __restrict__ adst,
              const float* __restrict__ bias, float* __restrict__ xout) {
    int g = blockIdx.x / kT, t = blockIdx.x % kT;
    __shared__ float xs[16][256];
    __shared__ float asr[256], ads[256];
    __shared__ float es[16][4], ed[16][4];
    __shared__ float alpha[16][16][4];
    int tid = threadIdx.x;
#pragma unroll
    for (int j = 0; j < 16; j++)
        xs[j][tid] = xl[(((size_t)(g * 16 + j)) * kT + t) * kFD + tid];
    asr[tid] = asrc[tid];
    ads[tid] = adst[tid];
    __syncthreads();
    if (tid < 128) {
        int half = tid >> 6, q = tid & 63;
        int j = q >> 2, h = q & 3;
        const float* av = half ? ads : asr;
        float acc = 0.f;
#pragma unroll
        for (int c = 0; c < 64; c++) acc += xs[j][h * 64 + c] * av[h * 64 + c];
        if (half) ed[j][h] = acc; else es[j][h] = acc;
    }
    __syncthreads();
    {
        int n = tid >> 4, j = tid & 15;
#pragma unroll
        for (int h = 0; h < 4; h++) {
            float e = es[j][h] + ed[n][h];
            e = e > 0.f ? e : 0.2f * e;
            float mx = e;
#pragma unroll
            for (int m = 8; m; m >>= 1) mx = fmaxf(mx, __shfl_xor_sync(0xffffffffu, mx, m));
            float ex = __expf(e - mx);
            float s = ex;
#pragma unroll
            for (int m = 8; m; m >>= 1) s += __shfl_xor_sync(0xffffffffu, s, m);
            alpha[n][j][h] = ex / s;
        }
    }
    __syncthreads();
    {
        int h = tid >> 6;
        float xv[16];
#pragma unroll
        for (int j = 0; j < 16; j++) xv[j] = xs[j][tid];
        float bv = bias[tid];
#pragma unroll
        for (int n = 0; n < 16; n++) {
            float acc = 0.f;
#pragma unroll
            for (int j = 0; j < 16; j++) acc += alpha[n][j][h] * xv[j];
            acc = fmaxf(acc + bv, 0.f);
            xout[(((size_t)(g * 16 + n)) * kT + t) * kFD + tid] = acc;
        }
    }
}

// ===================================================================
// Kernel D: GAT aggregation layer 1 — ONLY dst node 0 per group is needed
// (seq = x[::NA]). Output directly into seq (B,T,FD) layout.
// ===================================================================
__global__ __launch_bounds__(256)
void gat_agg1(const float* __restrict__ xl,
              const float* __restrict__ asrc, const float* __restrict__ adst,
              const float* __restrict__ bias, float* __restrict__ seq) {
    int g = blockIdx.x / kT, t = blockIdx.x % kT;
    __shared__ float xs[16][256];
    __shared__ float asr[256], ads[256];
    __shared__ float es[16][4];
    __shared__ float ed0[4];
    __shared__ float alpha[16][4];
    int tid = threadIdx.x;
#pragma unroll
    for (int j = 0; j < 16; j++)
        xs[j][tid] = xl[(((size_t)(g * 16 + j)) * kT + t) * kFD + tid];
    asr[tid] = asrc[tid];
    ads[tid] = adst[tid];
    __syncthreads();
    if (tid < 64) {
        int j = tid >> 2, h = tid & 3;
        float acc = 0.f;
#pragma unroll
        for (int c = 0; c < 64; c++) acc += xs[j][h * 64 + c] * asr[h * 64 + c];
        es[j][h] = acc;
    } else if (tid < 68) {
        int h = tid - 64;
        float acc = 0.f;
#pragma unroll
        for (int c = 0; c < 64; c++) acc += xs[0][h * 64 + c] * ads[h * 64 + c];
        ed0[h] = acc;
    }
    __syncthreads();
    if (tid < 32) {
        int j = tid & 15;
#pragma unroll
        for (int h = 0; h < 4; h++) {
            float e = es[j][h] + ed0[h];
            e = e > 0.f ? e : 0.2f * e;
            float mx = e;
#pragma unroll
            for (int m = 8; m; m >>= 1) mx = fmaxf(mx, __shfl_xor_sync(0xffffffffu, mx, m));
            float ex = __expf(e - mx);
            float s = ex;
#pragma unroll
            for (int m = 8; m; m >>= 1) s += __shfl_xor_sync(0xffffffffu, s, m);
            if (tid < 16) alpha[j][h] = ex / s;
        }
    }
    __syncthreads();
    {
        int h = tid >> 6;
        float acc = 0.f;
#pragma unroll
        for (int j = 0; j < 16; j++) acc += alpha[j][h] * xs[j][tid];
        seq[((size_t)g * kT + t) * kFD + tid] = fmaxf(acc + bias[tid], 0.f);
    }
}

// ===================================================================
// SGEMM: C(M,Nc) = A(M,K) @ W(Nc,K)^T (+bias). 128x128x16 tile, 8x8/thread.
// Requires M % 128 == 0, K % 16 == 0. Nc guarded.
// ===================================================================
__global__ __launch_bounds__(256)
void sgemm_bias(const float* __restrict__ Ain, const float* __restrict__ W,
                const float* __restrict__ bias, float* __restrict__ C,
                int M, int Nc, int K) {
    __shared__ float As[16][128];
    __shared__ float Bs[16][128];
    int tid = threadIdx.x;
    int row0 = blockIdx.x * 128;
    int col0 = blockIdx.y * 128;
    int tx = tid & 15, ty = tid >> 4;
    float acc[8][8];
#pragma unroll
    for (int i = 0; i < 8; i++)
#pragma unroll
        for (int j = 0; j < 8; j++) acc[i][j] = 0.f;

    for (int k0 = 0; k0 < K; k0 += 16) {
#pragma unroll
        for (int i = 0; i < 2; i++) {
            int f = tid + i * 256;
            int r = f >> 2;
            int kq = (f & 3) * 4;
            float4 v = *(const float4*)&Ain[(size_t)(row0 + r) * K + k0 + kq];
            As[kq + 0][r] = v.x; As[kq + 1][r] = v.y;
            As[kq + 2][r] = v.z; As[kq + 3][r] = v.w;
        }
#pragma unroll
        for (int i = 0; i < 2; i++) {
            int f = tid + i * 256;
            int r = f >> 2;
            int kq = (f & 3) * 4;
            int col = col0 + r;
            float4 v = make_float4(0.f, 0.f, 0.f, 0.f);
            if (col < Nc) v = *(const float4*)&W[(size_t)col * K + k0 + kq];
            Bs[kq + 0][r] = v.x; Bs[kq + 1][r] = v.y;
            Bs[kq + 2][r] = v.z; Bs[kq + 3][r] = v.w;
        }
        __syncthreads();
#pragma unroll
        for (int k = 0; k < 16; k++) {
            float4 a0 = *(const float4*)&As[k][ty * 8];
            float4 a1 = *(const float4*)&As[k][ty * 8 + 4];
            float4 b0 = *(const float4*)&Bs[k][tx * 8];
            float4 b1 = *(const float4*)&Bs[k][tx * 8 + 4];
            float av[8] = {a0.x, a0.y, a0.z, a0.w, a1.x, a1.y, a1.z, a1.w};
            float bv[8] = {b0.x, b0.y, b0.z, b0.w, b1.x, b1.y, b1.z, b1.w};
#pragma unroll
            for (int i = 0; i < 8; i++)
#pragma unroll
                for (int j = 0; j < 8; j++) acc[i][j] += av[i] * bv[j];
        }
        __syncthreads();
    }
#pragma unroll
    for (int i = 0; i < 8; i++) {
        int r = row0 + ty * 8 + i;
#pragma unroll
        for (int j = 0; j < 8; j++) {
            int c = col0 + tx * 8 + j;
            if (c < Nc) {
                float v = acc[i][j];
                if (bias) v += bias[c];
                C[(size_t)r * Nc + c] = v;
            }
        }
    }
}

// ===================================================================
// Attention: only q-row t=4 matters; additive 0/1 causal mask is constant
// (=1) on that row -> cancels in softmax. One block per batch b.
// ===================================================================
__global__ __launch_bounds__(256)
void attn_kernel(const float* __restrict__ qkv, float* __restrict__ ctx4) {
    int b = blockIdx.x;
    __shared__ float ks[kT][256], vs[kT][256], q4[256];
    __shared__ float sc[4][kT];
    __shared__ float attn[4][kT];
    int tid = threadIdx.x;
#pragma unroll
    for (int t = 0; t < kT; t++) {
        size_t base = ((size_t)(b * kT + t)) * (3 * kFD);
        ks[t][tid] = qkv[base + kFD + tid];
        vs[t][tid] = qkv[base + 2 * kFD + tid];
    }
    q4[tid] = qkv[((size_t)(b * kT + 4)) * (3 * kFD) + tid];
    __syncthreads();
    int warp = tid >> 5, lane = tid & 31;
    for (int p = warp; p < 4 * kT; p += 8) {
        int h = p / kT, kt = p % kT;
        float s = 0.f;
        for (int d = lane; d < 64; d += 32) s += q4[h * 64 + d] * ks[kt][h * 64 + d];
#pragma unroll
        for (int m = 16; m; m >>= 1) s += __shfl_xor_sync(0xffffffffu, s, m);
        if (lane == 0) sc[h][kt] = s * 0.125f;   // 1/sqrt(64)
    }
    __syncthreads();
    if (tid < 4) {
        float mx = -1e30f;
#pragma unroll
        for (int kt = 0; kt < kT; kt++) mx = fmaxf(mx, sc[tid][kt]);
        float e[kT], sum = 0.f;
#pragma unroll
        for (int kt = 0; kt < kT; kt++) { e[kt] = __expf(sc[tid][kt] - mx); sum += e[kt]; }
#pragma unroll
        for (int kt = 0; kt < kT; kt++) attn[tid][kt] = e[kt] / sum;
    }
    __syncthreads();
    int h = tid >> 6;
    float acc = 0.f;
#pragma unroll
    for (int kt = 0; kt < kT; kt++) acc += attn[h][kt] * vs[kt][tid];
    ctx4[(size_t)b * kFD + tid] = acc;
}

// ===================================================================
// Belief softmax: one warp per row of 64
// ===================================================================
__global__ __launch_bounds__(32)
void belief_softmax(const float* __restrict__ logits, float* __restrict__ out) {
    int b = blockIdx.x;
    int lane = threadIdx.x;
    float v0 = logits[(size_t)b * 64 + lane];
    float v1 = logits[(size_t)b * 64 + 32 + lane];
    float mx = fmaxf(v0, v1);
#pragma unroll
    for (int m = 16; m; m >>= 1) mx = fmaxf(mx, __shfl_xor_sync(0xffffffffu, mx, m));
    float e0 = __expf(v0 - mx), e1 = __expf(v1 - mx);
    float s = e0 + e1;
#pragma unroll
    for (int m = 16; m; m >>= 1) s += __shfl_xor_sync(0xffffffffu, s, m);
    out[(size_t)b * 64 + lane] = e0 / s;
    out[(size_t)b * 64 + 32 + lane] = e1 / s;
}

// ===================================================================
extern "C" void kernel_launch(void* const* d_in, const int* in_sizes, int n_in,
                              void* d_out, int out_size) {
    const float* signals = (const float*)d_in[0];
    const float* nact    = (const float*)d_in[1];
    const float* w0      = (const float*)d_in[2];
    const float* asrc0   = (const float*)d_in[3];
    const float* adst0   = (const float*)d_in[4];
    const float* bias0   = (const float*)d_in[5];
    const float* w1      = (const float*)d_in[6];
    const float* asrc1   = (const float*)d_in[7];
    const float* adst1   = (const float*)d_in[8];
    const float* bias1   = (const float*)d_in[9];
    const float* inw     = (const float*)d_in[10];
    const float* inb     = (const float*)d_in[11];
    const float* outw    = (const float*)d_in[12];
    const float* outb    = (const float*)d_in[13];
    const float* wmean   = (const float*)d_in[14];
    const float* bmean   = (const float*)d_in[15];
    const float* wlogv   = (const float*)d_in[16];
    const float* blogv   = (const float*)d_in[17];
    const float* wbel    = (const float*)d_in[18];
    const float* bbel    = (const float*)d_in[19];
    // d_in[20] = edge_index: graph is structural (dense 16 + self loops) -> unused
    float* out = (float*)d_out;

    float *xl0, *x1, *xl1, *seq, *qkv, *ctx4, *feat, *blg;
    cudaGetSymbolAddress((void**)&xl0,  g_xl0);
    cudaGetSymbolAddress((void**)&x1,   g_x1);
    cudaGetSymbolAddress((void**)&xl1,  g_xl1);
    cudaGetSymbolAddress((void**)&seq,  g_seq);
    cudaGetSymbolAddress((void**)&qkv,  g_qkv);
    cudaGetSymbolAddress((void**)&ctx4, g_ctx4);
    cudaGetSymbolAddress((void**)&feat, g_feat);
    cudaGetSymbolAddress((void**)&blg,  g_blog);

    // 1. node features + layer-0 linear (sparse-aware)
    build_lin0<<<kN, 256>>>(signals, nact, w0, xl0);
    // 2. GAT-0 aggregation + bias + relu
    gat_agg0<<<kB * kT, 256>>>(xl0, asrc0, adst0, bias0, x1);
    // 3. layer-1 linear (the big GEMM): xl1 = x1 @ w1^T
    sgemm_bias<<<dim3(kM / 128, kFD / 128), 256>>>(x1, w1, nullptr, xl1, kM, kFD, kFD);
    // 4. GAT-1 aggregation, dst node 0 only -> seq
    gat_agg1<<<kB * kT, 256>>>(xl1, asrc1, adst1, bias1, seq);
    // 5. qkv projection
    sgemm_bias<<<dim3((kB * kT) / 128, (3 * kFD) / 128), 256>>>(seq, inw, inb, qkv,
                                                                kB * kT, 3 * kFD, kFD);
    // 6. attention (q row t=4 only)
    attn_kernel<<<kB, 256>>>(qkv, ctx4);
    // 7. out_proj
    sgemm_bias<<<dim3(kB / 128, kFD / 128), 256>>>(ctx4, outw, outb, feat, kB, kFD, kFD);
    // 8-10. heads
    sgemm_bias<<<dim3(kB / 128, 1), 256>>>(feat, wmean, bmean, out, kB, kLAT, kFD);
    sgemm_bias<<<dim3(kB / 128, 1), 256>>>(feat, wlogv, blogv, out + (size_t)kB * kLAT,
                                           kB, kLAT, kFD);
    sgemm_bias<<<dim3(kB / 128, 1), 256>>>(feat, wbel, bbel, blg, kB, kS, kFD);
    // 11. belief softmax
    belief_softmax<<<kB, 32>>>(blg, out + (size_t)2 * kB * kLAT);
}